// round 16
// baseline (speedup 1.0000x reference)
#include <cuda_runtime.h>
#include <math.h>

// Problem constants
#define B 32
#define S 2048
#define D 1024
#define MASK_PENALTY 100000000.0f

// Tiling
#define NSPLIT 16
#define WARPS 8
#define THREADS (WARPS * 32)                    // 256
#define ROWS_PER_SPLIT (S / NSPLIT)             // 128

// Softmax tail cutoff: rows with score < M - DELTA contribute < e^-25 each
// (2048 * e^-25 ~ 3e-8 total relative weight mass; threshold is 1e-3).
#define DELTA 25.0f

// Scratch (allocation-free: __device__ globals, zero-init)
__device__ float g_score[B * S];      // 256 KB: per-row scores (-inf = masked)
__device__ float g_tm[B * NSPLIT];    // per-tile max
__device__ int   g_cnt[B];            // zero-init; self-resets each launch

// ---------------------------------------------------------------------------
// SCORES-THEN-SELECT attention.
// Phase A (all CTAs): compacted valid rows, warp-per-row DOT ONLY (no
//   accumulator state -> ~64 regs, 4 CTAs/SM, max streaming occupancy).
//   Scores written to global; masked rows get -inf.
// Epilogue (last CTA per batch): global max M, EXACT L over all scores,
//   deterministic selection of rows with score > M - DELTA (typically 1-5
//   rows), weighted accumulation of only those rows, write output.
// ---------------------------------------------------------------------------
__global__ void __launch_bounds__(THREADS)
attn_fused(const float* __restrict__ target,
           const float* __restrict__ context,
           const float* __restrict__ mask,
           float* __restrict__ out)
{
    const int b     = blockIdx.x;
    const int split = blockIdx.y;
    const int w     = threadIdx.x >> 5;
    const int lane  = threadIdx.x & 31;
    const int s0    = split * ROWS_PER_SPLIT;

    __shared__ short slist[ROWS_PER_SPLIT];
    __shared__ int   swcnt[4];
    __shared__ int   scnt;
    __shared__ float sscore[ROWS_PER_SPLIT];   // scores by list position
    __shared__ float sred[WARPS];
    // Epilogue-only (last CTA per batch):
    __shared__ float bscore[S];                // 8 KB
    __shared__ short bsel[S];                  // 4 KB, per-warp segments
    __shared__ int   bcnt[WARPS];

    // ---- Deterministic compaction of valid rows ----
    bool myv = false;
    int  mypos = 0;
    if (threadIdx.x < ROWS_PER_SPLIT)
        myv = mask[(size_t)b * S + s0 + threadIdx.x] != 0.f;
    const unsigned bal = __ballot_sync(0xffffffffu, myv);
    if (lane == 0 && w < 4) swcnt[w] = __popc(bal);
    __syncthreads();
    if (threadIdx.x == 0) scnt = swcnt[0] + swcnt[1] + swcnt[2] + swcnt[3];
    if (myv) {
        int off = 0;
#pragma unroll
        for (int i = 0; i < 4; i++) off += (i < w) ? swcnt[i] : 0;
        mypos = off + __popc(bal & ((1u << lane) - 1u));
        slist[mypos] = (short)threadIdx.x;
    }

    // Lane's slice of the query vector (registers)
    const float4* tg = (const float4*)(target + (size_t)b * D);
    float4 t[8];
#pragma unroll
    for (int i = 0; i < 8; i++) t[i] = tg[lane + 32 * i];

    __syncthreads();
    const int cnt = scnt;
    const float* cb = context + (size_t)b * S * D;

    // ================= Phase A: scores only (2 rows/iteration) =============
    for (int p = w; p < cnt; p += 2 * WARPS) {
        const int p2 = p + WARPS;
        const bool has2 = (p2 < cnt);
        const int r1 = slist[p];
        const int r2 = slist[has2 ? p2 : p];
        const float4* row1 = (const float4*)(cb + (size_t)(s0 + r1) * D);
        const float4* row2 = (const float4*)(cb + (size_t)(s0 + r2) * D);

        float4 c1[8], c2[8];
#pragma unroll
        for (int i = 0; i < 8; i++) c1[i] = row1[lane + 32 * i];
#pragma unroll
        for (int i = 0; i < 8; i++) c2[i] = row2[lane + 32 * i];

        float a0 = 0.f, a1 = 0.f, b0 = 0.f, b1 = 0.f;
#pragma unroll
        for (int i = 0; i < 8; i++) {
            a0 = fmaf(c1[i].x, t[i].x, a0);
            a1 = fmaf(c1[i].y, t[i].y, a1);
            a0 = fmaf(c1[i].z, t[i].z, a0);
            a1 = fmaf(c1[i].w, t[i].w, a1);
            b0 = fmaf(c2[i].x, t[i].x, b0);
            b1 = fmaf(c2[i].y, t[i].y, b1);
            b0 = fmaf(c2[i].z, t[i].z, b0);
            b1 = fmaf(c2[i].w, t[i].w, b1);
        }
        float dot1 = a0 + a1;
        float dot2 = b0 + b1;
#pragma unroll
        for (int off = 16; off > 0; off >>= 1) {
            dot1 += __shfl_xor_sync(0xffffffffu, dot1, off);
            dot2 += __shfl_xor_sync(0xffffffffu, dot2, off);
        }
        if (lane == 0) {
            sscore[p] = dot1;
            if (has2) sscore[p2] = dot2;
        }
    }
    __syncthreads();

    // ---- Tile max + publish scores ----
    float sv = (threadIdx.x < cnt) ? sscore[threadIdx.x] : -INFINITY;
    float smax = sv;
#pragma unroll
    for (int off = 16; off > 0; off >>= 1)
        smax = fmaxf(smax, __shfl_xor_sync(0xffffffffu, smax, off));
    if (lane == 0) sred[w] = smax;
    __syncthreads();
    if (threadIdx.x == 0) {
        float Mt = sred[0];
#pragma unroll
        for (int i = 1; i < WARPS; i++) Mt = fmaxf(Mt, sred[i]);
        g_tm[b * NSPLIT + split] = Mt;
    }
    if (threadIdx.x < ROWS_PER_SPLIT)
        g_score[(size_t)b * S + s0 + threadIdx.x] =
            myv ? sscore[mypos] : -INFINITY;

    // ---- Last CTA per batch runs the epilogue ----
    __threadfence();
    __syncthreads();
    __shared__ int isLast;
    if (threadIdx.x == 0)
        isLast = (atomicAdd(&g_cnt[b], 1) == NSPLIT - 1);
    __syncthreads();
    if (!isLast) return;
    __threadfence();  // acquire

    // Global max over tile maxes (finite: row 0 of each batch is valid)
    float M = -INFINITY;
#pragma unroll
    for (int p = 0; p < NSPLIT; p++)
        M = fmaxf(M, __ldcg(&g_tm[b * NSPLIT + p]));

    // Load all scores into smem (8 per thread)
#pragma unroll
    for (int k = 0; k < S / THREADS; k++)
        bscore[threadIdx.x + k * THREADS] =
            __ldcg(&g_score[(size_t)b * S + threadIdx.x + k * THREADS]);
    __syncthreads();

    // Exact L = sum exp(s - M) over ALL rows (masked: exp(-inf)=0)
    float lsum = 0.f;
#pragma unroll
    for (int k = 0; k < S / THREADS; k++)
        lsum += __expf(bscore[threadIdx.x + k * THREADS] - M);
#pragma unroll
    for (int off = 16; off > 0; off >>= 1)
        lsum += __shfl_xor_sync(0xffffffffu, lsum, off);
    if (lane == 0) sred[w] = lsum;
    __syncthreads();
    float L = 0.f;
#pragma unroll
    for (int i = 0; i < WARPS; i++) L += sred[i];
    const float Linv = 1.f / L;

    // Deterministic selection: warp w scans rows [w*256, (w+1)*256)
    const float thr = M - DELTA;
    {
        int base = 0;
#pragma unroll
        for (int r = 0; r < 8; r++) {
            const int idx = w * 256 + r * 32 + lane;
            const bool sel = bscore[idx] > thr;
            const unsigned sb = __ballot_sync(0xffffffffu, sel);
            if (sel) {
                const int pos = base + __popc(sb & ((1u << lane) - 1u));
                bsel[w * 256 + pos] = (short)idx;
            }
            base += __popc(sb);
        }
        if (lane == 0) bcnt[w] = base;
    }
    __syncthreads();

    // Prefetch selected rows into L2 (warp-parallel)
    for (int wg = 0; wg < WARPS; wg++)
        for (int k = 0; k < bcnt[wg]; k++) {
            const short row = bsel[wg * 256 + k];
            asm volatile("prefetch.global.L2 [%0];"
                         :: "l"((const char*)(cb + (size_t)row * D)
                                + 128u * (threadIdx.x & 31)));
        }

    // Accumulate the selected rows (deterministic order), 1 float4/thread
    const int d4 = threadIdx.x;
    float4 a = make_float4(0.f, 0.f, 0.f, 0.f);
    for (int wg = 0; wg < WARPS; wg++) {
        const int c = bcnt[wg];
        for (int k = 0; k < c; k++) {
            const short row = bsel[wg * 256 + k];
            const float wgt = __expf(bscore[row] - M);
            const float4 v = ((const float4*)(cb + (size_t)row * D))[d4];
            a.x = fmaf(wgt, v.x, a.x);
            a.y = fmaf(wgt, v.y, a.y);
            a.z = fmaf(wgt, v.z, a.z);
            a.w = fmaf(wgt, v.w, a.w);
        }
    }
    a.x *= Linv; a.y *= Linv; a.z *= Linv; a.w *= Linv;
    ((float4*)(out + (size_t)b * D))[d4] = a;

    if (threadIdx.x == 0) atomicExch(&g_cnt[b], 0);
}

extern "C" void kernel_launch(void* const* d_in, const int* in_sizes, int n_in,
                              void* d_out, int out_size)
{
    const float* target  = (const float*)d_in[0];  // [B, D]
    const float* context = (const float*)d_in[1];  // [B, S, D]
    const float* mask    = (const float*)d_in[2];  // [B, S]
    float* out = (float*)d_out;                    // [B, D]

    dim3 grid(B, NSPLIT);
    attn_fused<<<grid, THREADS>>>(target, context, mask, out);
}

// round 17
// speedup vs baseline: 1.2970x; 1.2970x over previous
#include <cuda_runtime.h>
#include <math.h>

// Problem constants
#define B 32
#define S 2048
#define D 1024
#define MASK_PENALTY 100000000.0f

// Tiling: ONE resident wave (B*NSPLIT = 256 CTAs @ 2/SM on 148 SMs)
#define NSPLIT 8
#define WARPS 8
#define THREADS (WARPS * 32)                    // 256
#define ROWS_PER_SPLIT (S / NSPLIT)             // 256 == THREADS
#define NSLOTS 3                                // per-warp smem ring depth
#define ROW_BYTES (D * 4)                       // 4096

#define SLOTS_BYTES (WARPS * NSLOTS * ROW_BYTES)   // 96 KB dynamic smem

// Scratch (allocation-free: __device__ globals, zero-init)
__device__ float g_m[B * NSPLIT];
__device__ float g_l[B * NSPLIT];
__device__ __align__(16) float g_acc[(size_t)B * NSPLIT * D];  // 1 MB
__device__ int g_cnt[B];  // zero-init; self-resets each launch

// ---- mbarrier / bulk-copy helpers ----
__device__ __forceinline__ unsigned smem_u32(const void* p) {
    return (unsigned)__cvta_generic_to_shared(p);
}
__device__ __forceinline__ void mbar_init(unsigned mbar, unsigned count) {
    asm volatile("mbarrier.init.shared.b64 [%0], %1;" :: "r"(mbar), "r"(count)
                 : "memory");
}
__device__ __forceinline__ void mbar_expect_tx(unsigned mbar, unsigned bytes) {
    asm volatile("mbarrier.arrive.expect_tx.shared.b64 _, [%0], %1;"
                 :: "r"(mbar), "r"(bytes) : "memory");
}
__device__ __forceinline__ void mbar_wait(unsigned mbar, unsigned phase) {
    asm volatile(
        "{\n\t.reg .pred P;\n\t"
        "WL_%=:\n\t"
        "mbarrier.try_wait.parity.acquire.cta.shared::cta.b64 P, [%0], %1, 0x989680;\n\t"
        "@!P bra WL_%=;\n\t"
        "}" :: "r"(mbar), "r"(phase) : "memory");
}
__device__ __forceinline__ void bulk_cp_4k(unsigned dst, const void* src,
                                           unsigned mbar) {
    asm volatile(
        "cp.async.bulk.shared::cluster.global.mbarrier::complete_tx::bytes "
        "[%0], [%1], %2, [%3];"
        :: "r"(dst), "l"(src), "r"((unsigned)ROW_BYTES), "r"(mbar) : "memory");
}

// ---------------------------------------------------------------------------
// Fused single-pass online-softmax attention: mask skipping + compaction +
// per-warp cp.async.bulk smem ring, SINGLE-WAVE GRID (256 CTAs, all resident
// simultaneously -> one ring prologue, no wave-transition bubble).
// Masked rows contribute exp(-1e8)==0.0f exactly in fp32 -> skipped.
// Each warp owns a contiguous chunk of the compacted valid-row list
// (ascending addresses) and a 3-slot x 4KB ring fed by lane-0 bulk copies
// (engine-driven HBM->SMEM, zero register/scoreboard coupling).
// 8 warp partials merge in smem (ring reused) -> 1 per CTA -> last CTA per
// batch merges the NSPLIT split partials (no second kernel).
// ---------------------------------------------------------------------------
__global__ void __launch_bounds__(THREADS)
attn_fused(const float* __restrict__ target,
           const float* __restrict__ context,
           const float* __restrict__ mask,
           float* __restrict__ out)
{
    extern __shared__ __align__(128) char slots[];   // [WARPS][NSLOTS][4096]

    const int b     = blockIdx.x;
    const int split = blockIdx.y;
    const int w     = threadIdx.x >> 5;
    const int lane  = threadIdx.x & 31;
    const int s0    = split * ROWS_PER_SPLIT;

    __shared__ __align__(8) unsigned long long mbar_s[WARPS][NSLOTS];
    __shared__ short slist[ROWS_PER_SPLIT];   // 256 entries
    __shared__ int   swcnt[WARPS];
    __shared__ int   scnt;
    __shared__ float sm_[WARPS];
    __shared__ float sl_[WARPS];

    // ---- Barrier init + deterministic compaction (256 threads, 1 row each)
    if (threadIdx.x < WARPS * NSLOTS)
        mbar_init(smem_u32(&mbar_s[threadIdx.x / NSLOTS][threadIdx.x % NSLOTS]), 1);

    const bool v = mask[(size_t)b * S + s0 + threadIdx.x] != 0.f;
    const unsigned bal = __ballot_sync(0xffffffffu, v);
    if (lane == 0) swcnt[w] = __popc(bal);
    __syncthreads();

    if (threadIdx.x == 0) {
        int tot = 0;
#pragma unroll
        for (int i = 0; i < WARPS; i++) tot += swcnt[i];
        scnt = tot;
    }
    if (v) {
        int off = 0;
#pragma unroll
        for (int i = 0; i < WARPS; i++) off += (i < w) ? swcnt[i] : 0;
        const int pos = off + __popc(bal & ((1u << lane) - 1u));
        slist[pos] = (short)threadIdx.x;
    }

    // Lane's slice of the query vector (registers)
    const float4* tg = (const float4*)(target + (size_t)b * D);
    float4 t[8];
#pragma unroll
    for (int i = 0; i < 8; i++) t[i] = tg[lane + 32 * i];

    __syncthreads();
    const int cnt = scnt;
    const float* cb = context + (size_t)b * S * D;

    // Per-warp CONTIGUOUS chunk of the compacted list (ascending addresses)
    const int begin = (cnt * w) / WARPS;
    const int end   = (cnt * (w + 1)) / WARPS;
    const int nrows = end - begin;

    // This warp's ring
    char* wslot = slots + (size_t)w * NSLOTS * ROW_BYTES;
    const unsigned slot_u32 = smem_u32(wslot);
    unsigned mb[NSLOTS];
#pragma unroll
    for (int k = 0; k < NSLOTS; k++) mb[k] = smem_u32(&mbar_s[w][k]);

    // Prologue: lane 0 issues bulk copies for the first NSLOTS rows (in order)
    if (lane == 0) {
#pragma unroll
        for (int k = 0; k < NSLOTS; k++) {
            if (k < nrows) {
                mbar_expect_tx(mb[k], ROW_BYTES);
                bulk_cp_4k(slot_u32 + k * ROW_BYTES,
                           cb + (size_t)(s0 + slist[begin + k]) * D, mb[k]);
            }
        }
    }

    float4 acc[8];
#pragma unroll
    for (int i = 0; i < 8; i++) acc[i] = make_float4(0.f, 0.f, 0.f, 0.f);

    float m = -INFINITY;
    float l = 0.f;

    // ---- Mainloop: consume rows from the smem ring (ascending order) ----
    for (int i = 0; i < nrows; i++) {
        const int slot  = i % NSLOTS;
        const unsigned phase = (unsigned)((i / NSLOTS) & 1);

        mbar_wait(mb[slot], phase);

        const float4* sp = (const float4*)(wslot + slot * ROW_BYTES);
        float4 c[8];
#pragma unroll
        for (int j = 0; j < 8; j++) c[j] = sp[lane + 32 * j];

        // Refill this slot with the row NSLOTS iterations ahead.
        const int nn = i + NSLOTS;
        if (lane == 0 && nn < nrows) {
            mbar_expect_tx(mb[slot], ROW_BYTES);
            bulk_cp_4k(slot_u32 + slot * ROW_BYTES,
                       cb + (size_t)(s0 + slist[begin + nn]) * D, mb[slot]);
        }

        // dot(context_row, target) for this lane's slice (2 chains)
        float d0 = 0.f, d1 = 0.f;
#pragma unroll
        for (int j = 0; j < 8; j++) {
            d0 = fmaf(c[j].x, t[j].x, d0);
            d1 = fmaf(c[j].y, t[j].y, d1);
            d0 = fmaf(c[j].z, t[j].z, d0);
            d1 = fmaf(c[j].w, t[j].w, d1);
        }
        float dot = d0 + d1;
#pragma unroll
        for (int off = 16; off > 0; off >>= 1)
            dot += __shfl_xor_sync(0xffffffffu, dot, off);

        // online softmax update (valid row => mask penalty term is 0)
        const float mnew  = fmaxf(m, dot);
        const float scale = __expf(m - mnew);     // 0 on first valid row
        const float wgt   = __expf(dot - mnew);
        l = l * scale + wgt;
#pragma unroll
        for (int j = 0; j < 8; j++) {
            acc[j].x = fmaf(acc[j].x, scale, wgt * c[j].x);
            acc[j].y = fmaf(acc[j].y, scale, wgt * c[j].y);
            acc[j].z = fmaf(acc[j].z, scale, wgt * c[j].z);
            acc[j].w = fmaf(acc[j].w, scale, wgt * c[j].w);
        }
        m = mnew;
    }

    // ---- In-CTA merge of the 8 warp partials (ring memory reused) ----
    if (lane == 0) { sm_[w] = m; sl_[w] = l; }
    __syncthreads();   // all warps done with their ring slots

    float Mcta = -INFINITY;
#pragma unroll
    for (int i = 0; i < WARPS; i++) Mcta = fmaxf(Mcta, sm_[i]);

    float4* sacc = (float4*)slots;   // [WARPS][D/4] = 32 KB within 96 KB
    const float f = (m > -INFINITY) ? __expf(m - Mcta) : 0.f;
#pragma unroll
    for (int i = 0; i < 8; i++) {
        float4 a = acc[i];
        a.x *= f; a.y *= f; a.z *= f; a.w *= f;
        sacc[w * (D / 4) + lane + 32 * i] = a;
    }
    __syncthreads();

    // 256 threads sum across the 8 warps, write CTA partial
    const int pidx = b * NSPLIT + split;
    const int d4 = threadIdx.x;
    float4 sum = sacc[d4];
#pragma unroll
    for (int i = 1; i < WARPS; i++) {
        const float4 vv = sacc[i * (D / 4) + d4];
        sum.x += vv.x; sum.y += vv.y; sum.z += vv.z; sum.w += vv.w;
    }
    ((float4*)(g_acc + (size_t)pidx * D))[d4] = sum;

    if (threadIdx.x == 0) {
        float L = 0.f;
#pragma unroll
        for (int i = 0; i < WARPS; i++)
            L += (sm_[i] > -INFINITY ? __expf(sm_[i] - Mcta) : 0.f) * sl_[i];
        g_m[pidx] = Mcta;   // -inf if the whole split is masked
        g_l[pidx] = L;
    }

    // ---- Last CTA per batch merges the NSPLIT partials ----
    __threadfence();
    __syncthreads();
    __shared__ int isLast;
    if (threadIdx.x == 0)
        isLast = (atomicAdd(&g_cnt[b], 1) == NSPLIT - 1);
    __syncthreads();
    if (!isLast) return;
    __threadfence();  // acquire

    float pm[NSPLIT], pl[NSPLIT];
#pragma unroll
    for (int p = 0; p < NSPLIT; p++) {
        pm[p] = __ldcg(&g_m[b * NSPLIT + p]);
        pl[p] = __ldcg(&g_l[b * NSPLIT + p]);
    }
    // M is finite: position 0 of every batch is guaranteed valid.
    float M = -INFINITY;
#pragma unroll
    for (int p = 0; p < NSPLIT; p++) M = fmaxf(M, pm[p]);
    float L = 0.f;
#pragma unroll
    for (int p = 0; p < NSPLIT; p++)
        L += (pm[p] > -INFINITY ? __expf(pm[p] - M) : 0.f) * pl[p];
    const float Linv = 1.f / L;

    float4 a = make_float4(0.f, 0.f, 0.f, 0.f);
#pragma unroll
    for (int p = 0; p < NSPLIT; p++) {
        const float fp = (pm[p] > -INFINITY) ? __expf(pm[p] - M) : 0.f;
        const float4 vv =
            __ldcg((const float4*)(g_acc + (size_t)(b * NSPLIT + p) * D) + d4);
        a.x = fmaf(fp, vv.x, a.x);
        a.y = fmaf(fp, vv.y, a.y);
        a.z = fmaf(fp, vv.z, a.z);
        a.w = fmaf(fp, vv.w, a.w);
    }
    a.x *= Linv; a.y *= Linv; a.z *= Linv; a.w *= Linv;
    ((float4*)(out + (size_t)b * D))[d4] = a;

    if (threadIdx.x == 0) atomicExch(&g_cnt[b], 0);
}

extern "C" void kernel_launch(void* const* d_in, const int* in_sizes, int n_in,
                              void* d_out, int out_size)
{
    const float* target  = (const float*)d_in[0];  // [B, D]
    const float* context = (const float*)d_in[1];  // [B, S, D]
    const float* mask    = (const float*)d_in[2];  // [B, S]
    float* out = (float*)d_out;                    // [B, D]

    cudaFuncSetAttribute(attn_fused,
                         cudaFuncAttributeMaxDynamicSharedMemorySize,
                         SLOTS_BYTES);

    dim3 grid(B, NSPLIT);   // 256 CTAs = one resident wave
    attn_fused<<<grid, THREADS, SLOTS_BYTES>>>(target, context, mask, out);
}